// round 12
// baseline (speedup 1.0000x reference)
#include <cuda_runtime.h>
#include <cub/cub.cuh>
#include <cstdint>

// Problem constants (B=8, L=1e6, C=4 -> size=1349)
#define SPIRAL_SIZE 1349
#define HALF        674
#define NCELL       (SPIRAL_SIZE * SPIRAL_SIZE)   // 1,819,801 < 2^21
#define SIGLEN      1000000
#define NBATCH      8

#define PI_F 3.14159274101257324f   // fl(pi)

// Validity cutoff (validated rel_err==0.0): rings 0..564 cover all ranks < 1e6.
#define KMAX   564
#define NRV    (KMAX + 1)           // 565 valid rings

#define RBKT   2048                 // smem buckets per ring
#define RT     512                  // ring_rank threads
#define SLOTCAP 3968                // >= max ring pop (~3544 + fluctuation)

#define STAGECAP 1310720            // > seg_off(NRV) ~ 1,292,300
#define HALF_ROWS   (HALF + 1)
#define HALF_CELLS  (HALF_ROWS * SPIRAL_SIZE)  // 910,575

__device__ uint32_t           g_ringCount[NRV];
__device__ unsigned long long g_staged[STAGECAP];
__device__ uint32_t           g_rank[NCELL];

extern "C" __device__ float __nv_atan2f(float, float);

// JAX acos: acos(x) = 2*atan2(sqrt(1-x*x), 1+x); exact pi at x==-1.
__device__ __forceinline__ float acos_jax(float xq) {
    if (xq == -1.0f) return PI_F;
    float t  = __fsub_rn(1.0f, __fmul_rn(xq, xq));
    float sq = __fsqrt_rn(t);
    return __fmul_rn(2.0f, __nv_atan2f(sq, __fadd_rn(1.0f, xq)));
}

// Analytic ring-segment offset: cumulative area pi*k^2 plus 512/ring slack.
// seg_off(k+1)-seg_off(k) ~ 2*pi*k + 512 >= ring population (fluct << 512).
__device__ __forceinline__ uint32_t seg_off(int k) {
    return (uint32_t)(3.141592653589793 * (double)k * (double)k + 0.5)
         + ((uint32_t)k << 9);
}

// Per-ring bucket mapping (validated). Keys of ring k lie in [T-pi, T+pi],
// T = fl(2k*pi); bound +-3.2 guarantees containment. (kb-lo)>>sh < 2048.
__device__ __forceinline__ void ring_map(int k, uint32_t& lo, int& sh) {
    float T   = __fmul_rn((float)(2 * k), PI_F);
    float lof = fmaxf(__fsub_rn(T, 3.2f), 0.0f);
    float hif = __fadd_rn(T, 3.2f);
    lo = __float_as_uint(lof);
    uint32_t span = __float_as_uint(hif) - lo;
    int bn = 32 - __clz(span | 1);
    sh = (bn > 11) ? (bn - 11) : 0;
}

// ---------------------------------------------------------------------------
// K1: dense over x2>=0 half-plane; one thread -> key for its cell AND mirror
// (bit-exact: r, xq, A identical; phi*sign(x2) is an exact sign flip).
// Ring-segment append with WARP-AGGREGATED atomics: lanes group by ring via
// match_any; one leader atomicAdd per (warp, ring) group; per-lane offsets
// from two ballots (cnt>=1, cnt==2). No early returns so warp intrinsics
// see the full warp.
// ---------------------------------------------------------------------------
__global__ __launch_bounds__(256) void key_kernel() {
    int tid  = blockIdx.x * blockDim.x + threadIdx.x;
    int lane = threadIdx.x & 31;

    int cnt = 0;
    int k = 0;
    uint32_t s = 0, sm = 0;
    uint32_t kb = 0, kbm = 0;

    if (tid < HALF_CELLS) {
        int di = tid / SPIRAL_SIZE;
        int j  = tid - di * SPIRAL_SIZE;
        int i  = HALF + di;

        float x1 = (float)(j - HALF);
        float x2 = (float)di;
        float rr = __fadd_rn(__fmul_rn(x1, x1), __fmul_rn(x2, x2));
        float r  = __fsqrt_rn(rr);
        k = (int)rintf(r);

        if (k <= KMAX) {
            float T = __fmul_rn(__fmul_rn(rintf(r), 2.0f), PI_F);
            s = (uint32_t)(i * SPIRAL_SIZE + j);
            if (di == 0) {
                // x2 == 0 row: phi = 0 (NaN-fixed center), +pi if x1 < 0.
                float phi = (x1 < 0.0f) ? PI_F : 0.0f;
                kb  = __float_as_uint(__fadd_rn(T, phi));
                cnt = 1;
            } else {
                float A = acos_jax(__fdiv_rn(x1, r));    // finite: r > 0
                kb  = __float_as_uint(__fadd_rn(T, A));  // phi = +A
                kbm = __float_as_uint(__fadd_rn(T, -A)); // mirror: phi = -A
                sm  = (uint32_t)((2 * HALF - i) * SPIRAL_SIZE + j);
                cnt = 2;
            }
        }
    }

    // Group lanes by ring (inactive lanes get unique keys so they never match).
    int mkey = (cnt > 0) ? k : (0x40000000 | lane);
    unsigned peers = __match_any_sync(0xFFFFFFFFu, mkey);
    unsigned b1 = __ballot_sync(0xFFFFFFFFu, cnt >= 1);
    unsigned b2 = __ballot_sync(0xFFFFFFFFu, cnt == 2);

    int leader = __ffs(peers) - 1;
    unsigned lowmask = (lane == 0) ? 0u : (0xFFFFFFFFu >> (32 - lane));
    uint32_t prefix = __popc(peers & b1 & lowmask) + __popc(peers & b2 & lowmask);
    uint32_t total  = __popc(peers & b1) + __popc(peers & b2);

    uint32_t base = 0;
    if (cnt > 0 && lane == leader)
        base = atomicAdd(&g_ringCount[k], total);
    base = __shfl_sync(0xFFFFFFFFu, base, leader);

    if (cnt > 0) {
        uint32_t pos = seg_off(k) + base + prefix;
        g_staged[pos] = ((unsigned long long)kb << 21) | s;
        if (cnt == 2)
            g_staged[pos + 1] = ((unsigned long long)kbm << 21) | sm;
    }
}

// ---------------------------------------------------------------------------
// K2: one block per ring. In-SM counting-sort rank:
//   ringStart = block-reduce of ringCount[0..k)
//   smem 2048-bucket hist -> block scan -> smem bucket scatter ->
//   rank = bucketStart + #{bucket peers with smaller packed value}
// Packed compare makes float-key ties index-stable == jnp.argsort (validated).
// Writes g_rank[s] = ringStart + within-ring rank.
// ---------------------------------------------------------------------------
__global__ __launch_bounds__(RT) void ring_rank_kernel() {
    extern __shared__ unsigned char dyn[];
    unsigned long long* slots = (unsigned long long*)dyn;          // SLOTCAP*8
    uint32_t* hist   = (uint32_t*)(dyn + SLOTCAP * 8);             // RBKT*4
    uint32_t* boff   = hist + RBKT;                                // RBKT*4
    uint32_t* cursor = boff + RBKT;                                // RBKT*4

    typedef cub::BlockScan<uint32_t, RT>  BS;
    typedef cub::BlockReduce<uint32_t, RT> BR;
    __shared__ union { typename BS::TempStorage scan;
                       typename BR::TempStorage red; } tmp;
    __shared__ uint32_t s_ringStart;

    const int k = blockIdx.x;
    const int t = threadIdx.x;

    // Ring start = total population of rings < k.
    uint32_t my = 0;
    for (int m = t; m < k; m += RT) my += g_ringCount[m];
    uint32_t rs = BR(tmp.red).Sum(my);
    if (t == 0) s_ringStart = rs;

    for (int b = t; b < RBKT; b += RT) hist[b] = 0;
    __syncthreads();

    const uint32_t n    = g_ringCount[k];
    const uint32_t base = seg_off(k);
    uint32_t lo; int sh;
    ring_map(k, lo, sh);

    // Pass 1: histogram (segment is L2-hot from key_kernel).
    for (uint32_t p = t; p < n; p += RT) {
        unsigned long long e = g_staged[base + p];
        uint32_t b = ((uint32_t)(e >> 21) - lo) >> sh;
        atomicAdd(&hist[b], 1u);
    }
    __syncthreads();

    // Exclusive scan of 2048 buckets (512 threads x 4).
    uint32_t c0 = hist[t * 4], c1 = hist[t * 4 + 1];
    uint32_t c2 = hist[t * 4 + 2], c3 = hist[t * 4 + 3];
    uint32_t ex;
    BS(tmp.scan).ExclusiveSum(c0 + c1 + c2 + c3, ex);
    boff[t * 4]     = ex; cursor[t * 4]     = ex; ex += c0;
    boff[t * 4 + 1] = ex; cursor[t * 4 + 1] = ex; ex += c1;
    boff[t * 4 + 2] = ex; cursor[t * 4 + 2] = ex; ex += c2;
    boff[t * 4 + 3] = ex; cursor[t * 4 + 3] = ex;
    __syncthreads();

    // Pass 2: bucket scatter into slots.
    for (uint32_t p = t; p < n; p += RT) {
        unsigned long long e = g_staged[base + p];
        uint32_t b   = ((uint32_t)(e >> 21) - lo) >> sh;
        uint32_t pos = atomicAdd(&cursor[b], 1u);
        if (pos < SLOTCAP) slots[pos] = e;
    }
    __syncthreads();

    // Pass 3: exact rank among bucket peers; write global rank.
    const uint32_t ringStart = s_ringStart;
    for (uint32_t p = t; p < n; p += RT) {
        unsigned long long e = slots[p];
        uint32_t b   = ((uint32_t)(e >> 21) - lo) >> sh;
        uint32_t st  = boff[b];
        uint32_t cnt = hist[b];
        uint32_t rank = st;
        if (cnt > 1) {
            for (uint32_t q = st; q < st + cnt; q++)
                rank += (slots[q] < e) ? 1u : 0u;
        }
        g_rank[(uint32_t)(e & 0x1FFFFFu)] = ringStart + rank;
    }
}

// ---------------------------------------------------------------------------
// K3: gather (measured-fastest form). Linear coalesced writes; one coalesced
// rank read; k-guard zeroes invalid rings (their g_rank is never written --
// the guard short-circuits, deterministic).
// ---------------------------------------------------------------------------
__global__ __launch_bounds__(256) void gather_kernel(
        const float4* __restrict__ in, float4* __restrict__ out,
        const uint32_t* __restrict__ rank_arr) {
    int s = blockIdx.x * blockDim.x + threadIdx.x;
    if (s >= NCELL) return;
    int i = s / SPIRAL_SIZE, j = s - i * SPIRAL_SIZE;
    float x1 = (float)(j - HALF), x2 = (float)(i - HALF);
    float r = __fsqrt_rn(__fadd_rn(__fmul_rn(x1, x1), __fmul_rn(x2, x2)));
    int k = (int)rintf(r);

    uint32_t rank = rank_arr[s];
    bool valid = (k <= KMAX) && (rank < (uint32_t)SIGLEN);

    float4 z = make_float4(0.0f, 0.0f, 0.0f, 0.0f);
#pragma unroll
    for (int b = 0; b < NBATCH; b++) {
        float4 w = z;
        if (valid) w = __ldg(&in[(size_t)b * SIGLEN + rank]);
        __stcs(&out[(size_t)b * NCELL + s], w);
    }
}

extern "C" void kernel_launch(void* const* d_in, const int* in_sizes, int n_in,
                              void* d_out, int out_size) {
    (void)in_sizes; (void)n_in; (void)out_size;

    void *cntp, *rankp;
    cudaGetSymbolAddress(&cntp,  g_ringCount);
    cudaGetSymbolAddress(&rankp, g_rank);

    const int DYN = SLOTCAP * 8 + 3 * RBKT * 4;   // 56,320 B
    cudaFuncSetAttribute(ring_rank_kernel,
                         cudaFuncAttributeMaxDynamicSharedMemorySize, DYN);

    cudaMemsetAsync(cntp, 0, NRV * sizeof(uint32_t), (cudaStream_t)0);

    key_kernel<<<(HALF_CELLS + 255) / 256, 256>>>();
    ring_rank_kernel<<<NRV, RT, DYN>>>();
    gather_kernel<<<(NCELL + 255) / 256, 256>>>(
        (const float4*)d_in[0], (float4*)d_out, (const uint32_t*)rankp);
}

// round 13
// speedup vs baseline: 1.0138x; 1.0138x over previous
#include <cuda_runtime.h>
#include <cub/cub.cuh>
#include <cstdint>

// Problem constants (B=8, L=1e6, C=4 -> size=1349)
#define SPIRAL_SIZE 1349
#define HALF        674
#define NCELL       (SPIRAL_SIZE * SPIRAL_SIZE)   // 1,819,801 < 2^21
#define SIGLEN      1000000
#define NBATCH      8

#define PI_F 3.14159274101257324f   // fl(pi)

// Validity cutoff (validated rel_err==0.0): rings 0..564 cover all ranks < 1e6.
#define KMAX   564
#define NRV    (KMAX + 1)
#define BPR    2048                 // buckets per ring
#define NBKT   (NRV * BPR)          // 1,157,120

#define SCAN_BLK   512
#define SCAN_ITEMS 4
#define SCAN_TILE  (SCAN_BLK * SCAN_ITEMS)  // 2048 == BPR
#define NTILES     (NBKT / SCAN_TILE)       // 565 exact

#define SORTCAP     1100000                 // > total valid cells (~1.0012M)
#define HALF_ROWS   (HALF + 1)
#define HALF_CELLS  (HALF_ROWS * SPIRAL_SIZE)  // 910,575

#define FLAG_INVALID 0u
#define FLAG_AGG     1u
#define FLAG_PREFIX  2u

__device__ uint32_t           g_hist16[NBKT / 2];   // two u16 counts per word
__device__ uint32_t           g_cursor[NBKT + 1];   // bucket starts + sentinel
__device__ uint32_t           g_kb[NCELL];
__device__ uint16_t           g_arr[NCELL];         // within-bucket arrival idx
__device__ unsigned long long g_sorted[SORTCAP];
__device__ volatile uint32_t  g_status[NTILES];     // (sum << 2) | flag
__device__ uint32_t           g_ticket;

extern "C" __device__ float __nv_atan2f(float, float);

// JAX acos: acos(x) = 2*atan2(sqrt(1-x*x), 1+x); exact pi at x==-1.
__device__ __forceinline__ float acos_jax(float xq) {
    if (xq == -1.0f) return PI_F;
    float t  = __fsub_rn(1.0f, __fmul_rn(xq, xq));
    float sq = __fsqrt_rn(t);
    return __fmul_rn(2.0f, __nv_atan2f(sq, __fadd_rn(1.0f, xq)));
}

// Per-ring bucket mapping. Keys of ring k lie in [T-pi, T+pi], T = fl(2k*pi);
// bound +-3.2 guarantees containment. (kb - lo) >> sh < 2048, monotone.
__device__ __forceinline__ void ring_map(int k, uint32_t& lo, int& sh) {
    float T   = __fmul_rn((float)(2 * k), PI_F);
    float lof = fmaxf(__fsub_rn(T, 3.2f), 0.0f);
    float hif = __fadd_rn(T, 3.2f);
    lo = __float_as_uint(lof);
    uint32_t span = __float_as_uint(hif) - lo;
    int bn = 32 - __clz(span | 1);
    sh = (bn > 11) ? (bn - 11) : 0;
}

// K0: zero histogram + scan bookkeeping.
__global__ void zero_kernel() {
    int t = blockIdx.x * blockDim.x + threadIdx.x;
    if (t < NBKT / 8) ((uint4*)g_hist16)[t] = make_uint4(0, 0, 0, 0);
    if (t < NTILES) g_status[t] = FLAG_INVALID;
    if (t == 0) g_ticket = 0;
}

// ---------------------------------------------------------------------------
// K1: dense over x2>=0 half-plane; one thread -> key for its cell AND mirror
// (bit-exact: r, xq, A identical; phi*sign(x2) is an exact sign flip).
// The histogram atomicAdd's OLD value = within-bucket arrival index (g_arr).
// ---------------------------------------------------------------------------
__global__ __launch_bounds__(256) void key_kernel() {
    int tid = blockIdx.x * blockDim.x + threadIdx.x;
    if (tid >= HALF_CELLS) return;
    int di = tid / SPIRAL_SIZE;
    int j  = tid - di * SPIRAL_SIZE;
    int i  = HALF + di;

    float x1 = (float)(j - HALF);
    float x2 = (float)di;
    float rr = __fadd_rn(__fmul_rn(x1, x1), __fmul_rn(x2, x2));
    float r  = __fsqrt_rn(rr);
    int   k  = (int)rintf(r);
    if (k > KMAX) return;

    float T = __fmul_rn(__fmul_rn(rintf(r), 2.0f), PI_F);
    uint32_t lo; int sh;
    ring_map(k, lo, sh);
    uint32_t bb = (uint32_t)k * BPR;

    int s = i * SPIRAL_SIZE + j;

    if (di == 0) {
        float phi = (x1 < 0.0f) ? PI_F : 0.0f;   // x2==0 row (NaN-fixed center)
        uint32_t kb = __float_as_uint(__fadd_rn(T, phi));
        g_kb[s] = kb;
        uint32_t b   = bb + ((kb - lo) >> sh);
        uint32_t old = atomicAdd(&g_hist16[b >> 1], 1u << ((b & 1u) * 16u));
        g_arr[s] = (uint16_t)((old >> ((b & 1u) * 16u)) & 0xFFFFu);
        return;
    }

    float A = acos_jax(__fdiv_rn(x1, r));

    uint32_t kb = __float_as_uint(__fadd_rn(T, A));      // phi = +A
    g_kb[s] = kb;
    uint32_t b   = bb + ((kb - lo) >> sh);
    uint32_t old = atomicAdd(&g_hist16[b >> 1], 1u << ((b & 1u) * 16u));
    g_arr[s] = (uint16_t)((old >> ((b & 1u) * 16u)) & 0xFFFFu);

    int sm = (2 * HALF - i) * SPIRAL_SIZE + j;
    uint32_t kbm = __float_as_uint(__fadd_rn(T, -A));    // mirror: phi = -A
    g_kb[sm] = kbm;
    uint32_t bm   = bb + ((kbm - lo) >> sh);
    uint32_t oldm = atomicAdd(&g_hist16[bm >> 1], 1u << ((bm & 1u) * 16u));
    g_arr[sm] = (uint16_t)((oldm >> ((bm & 1u) * 16u)) & 0xFFFFu);
}

// ---------------------------------------------------------------------------
// K2: single-pass exclusive scan hist16 -> g_cursor (decoupled lookback,
// ticket-ordered tiles). Last tile writes the sentinel g_cursor[NBKT].
// ---------------------------------------------------------------------------
__global__ __launch_bounds__(SCAN_BLK) void scan_kernel() {
    typedef cub::BlockScan<uint32_t, SCAN_BLK> BS;
    __shared__ typename BS::TempStorage tmp;
    __shared__ uint32_t s_tile;
    __shared__ uint32_t s_exclusive;

    if (threadIdx.x == 0) s_tile = atomicAdd(&g_ticket, 1u);
    __syncthreads();
    const uint32_t tile = s_tile;
    const int t = threadIdx.x;

    int wbase = (tile * SCAN_TILE + t * SCAN_ITEMS) >> 1;
    uint2 w = ((const uint2*)g_hist16)[wbase >> 1];
    uint32_t c0 = w.x & 0xFFFFu, c1 = w.x >> 16;
    uint32_t c2 = w.y & 0xFFFFu, c3 = w.y >> 16;
    uint32_t sum = c0 + c1 + c2 + c3;

    uint32_t tb, block_total;
    BS(tmp).ExclusiveSum(sum, tb, block_total);

    if (t == 0)
        g_status[tile] = (block_total << 2) |
                         (tile == 0 ? FLAG_PREFIX : FLAG_AGG);

    if (tile == 0) {
        if (t == 0) s_exclusive = 0;
    } else if (t < 32) {
        uint32_t excl = 0;
        int base = (int)tile;
        for (;;) {
            int idx = base - 32 + t;
            uint32_t st;
            if (idx >= 0) {
                do { st = g_status[idx]; } while ((st & 3u) == FLAG_INVALID);
            } else {
                st = FLAG_PREFIX;            // virtual zero-prefix before tile 0
            }
            uint32_t pmask = __ballot_sync(0xFFFFFFFFu, (st & 3u) == FLAG_PREFIX);
            int hp = 31 - __clz(pmask);
            uint32_t contrib = (t >= hp) ? (st >> 2) : 0u;
#pragma unroll
            for (int d = 16; d > 0; d >>= 1)
                contrib += __shfl_down_sync(0xFFFFFFFFu, contrib, d);
            contrib = __shfl_sync(0xFFFFFFFFu, contrib, 0);
            excl += contrib;
            if (pmask) break;
            base -= 32;
        }
        if (t == 0) {
            s_exclusive = excl;
            g_status[tile] = ((excl + block_total) << 2) | FLAG_PREFIX;
        }
    }
    __syncthreads();

    uint32_t run = s_exclusive + tb;
    uint4 o;
    o.x = run; run += c0;
    o.y = run; run += c1;
    o.z = run; run += c2;
    o.w = run;
    ((uint4*)g_cursor)[(tile * SCAN_TILE + t * SCAN_ITEMS) >> 2] = o;

    if (tile == NTILES - 1 && t == 0)
        g_cursor[NBKT] = s_exclusive + block_total;   // sentinel: total count
}

// K3: atomic-free scatter. pos = cursor[b] + arrival idx (unique); cursor
// stays pristine = exact bucket-start table for the gather. Staging only.
__global__ __launch_bounds__(256) void scatter_kernel() {
    int s = blockIdx.x * blockDim.x + threadIdx.x;
    if (s >= NCELL) return;
    int i = s / SPIRAL_SIZE, j = s - i * SPIRAL_SIZE;
    float x1 = (float)(j - HALF), x2 = (float)(i - HALF);
    float r = __fsqrt_rn(__fadd_rn(__fmul_rn(x1, x1), __fmul_rn(x2, x2)));
    int k = (int)rintf(r);
    if (k > KMAX) return;
    uint32_t lo; int sh;
    ring_map(k, lo, sh);
    uint32_t kb = g_kb[s];
    uint32_t b  = (uint32_t)k * BPR + ((kb - lo) >> sh);
    uint32_t pos = g_cursor[b] + (uint32_t)g_arr[s];
    g_sorted[pos] = ((unsigned long long)kb << 21) | (uint32_t)s;
}

// ---------------------------------------------------------------------------
// Per-cell rank resolution (validated rule): rank = cursor[b] + #{bucket
// peers with smaller packed value}; index-stable ties == jnp.argsort.
// ---------------------------------------------------------------------------
__device__ __forceinline__ bool resolve_rank(int s, uint32_t& rank) {
    int i = s / SPIRAL_SIZE, j = s - i * SPIRAL_SIZE;
    float x1 = (float)(j - HALF), x2 = (float)(i - HALF);
    float r = __fsqrt_rn(__fadd_rn(__fmul_rn(x1, x1), __fmul_rn(x2, x2)));
    int k = (int)rintf(r);
    if (k > KMAX) return false;
    uint32_t lo; int sh;
    ring_map(k, lo, sh);
    uint32_t kb  = g_kb[s];
    uint32_t b   = (uint32_t)k * BPR + ((kb - lo) >> sh);
    uint32_t st  = g_cursor[b];
    uint32_t end = g_cursor[b + 1];
    rank = st;
    if (end - st > 1) {
        unsigned long long my = ((unsigned long long)kb << 21) | (uint32_t)s;
        for (uint32_t q = st; q < end; q++)
            rank += (g_sorted[q] < my) ? 1u : 0u;
    }
    return rank < (uint32_t)SIGLEN;
}

// ---------------------------------------------------------------------------
// K4: fused rank + gather, LINEAR cell order, TWO adjacent cells per thread:
//  - 16 independent input loads in flight (2x MLP vs one-cell version)
//  - 32B contiguous store per (thread, batch) = exactly one sector
//  - ring-arc-adjacent cell pairs share input 32B sectors (ranks r, r+1)
// Input via __ldcg (L2-only; once-read stream should not occupy L1).
// ---------------------------------------------------------------------------
__global__ __launch_bounds__(256) void gather_kernel(
        const float4* __restrict__ in, float4* __restrict__ out) {
    int s0 = (blockIdx.x * blockDim.x + threadIdx.x) * 2;
    if (s0 >= NCELL) return;
    bool has1 = (s0 + 1 < NCELL);

    uint32_t r0 = 0, r1 = 0;
    bool v0 = resolve_rank(s0, r0);
    bool v1 = has1 ? resolve_rank(s0 + 1, r1) : false;

    float4 z = make_float4(0.0f, 0.0f, 0.0f, 0.0f);
#pragma unroll
    for (int b = 0; b < NBATCH; b++) {
        float4 w0 = z, w1 = z;
        if (v0) w0 = __ldcg(&in[(size_t)b * SIGLEN + r0]);
        if (v1) w1 = __ldcg(&in[(size_t)b * SIGLEN + r1]);
        __stcs(&out[(size_t)b * NCELL + s0], w0);
        if (has1) __stcs(&out[(size_t)b * NCELL + s0 + 1], w1);
    }
}

extern "C" void kernel_launch(void* const* d_in, const int* in_sizes, int n_in,
                              void* d_out, int out_size) {
    (void)in_sizes; (void)n_in; (void)out_size;

    zero_kernel<<<(NBKT / 8 + 255) / 256, 256>>>();
    key_kernel<<<(HALF_CELLS + 255) / 256, 256>>>();
    scan_kernel<<<NTILES, SCAN_BLK>>>();
    scatter_kernel<<<(NCELL + 255) / 256, 256>>>();

    gather_kernel<<<(NCELL / 2 + 256) / 256, 256>>>(
        (const float4*)d_in[0], (float4*)d_out);
}

// round 15
// speedup vs baseline: 1.1946x; 1.1784x over previous
#include <cuda_runtime.h>
#include <cub/cub.cuh>
#include <cstdint>

// Problem constants (B=8, L=1e6, C=4 -> size=1349)
#define SPIRAL_SIZE 1349
#define HALF        674
#define NCELL       (SPIRAL_SIZE * SPIRAL_SIZE)   // 1,819,801 < 2^21
#define SIGLEN      1000000
#define NBATCH      8

#define PI_F 3.14159274101257324f   // fl(pi)

// Validity cutoff (validated rel_err==0.0): rings 0..564 cover all ranks < 1e6.
#define KMAX   564
#define NRV    (KMAX + 1)
#define BPR    2048                 // buckets per ring
#define NBKT   (NRV * BPR)          // 1,157,120

#define SCAN_BLK   512
#define SCAN_ITEMS 4
#define SCAN_TILE  (SCAN_BLK * SCAN_ITEMS)  // 2048 == BPR
#define NTILES     (NBKT / SCAN_TILE)       // 565 exact

#define SORTCAP     1100000                 // > total valid cells (~1.0012M)
#define HALF_ROWS   (HALF + 1)
#define HALF_CELLS  (HALF_ROWS * SPIRAL_SIZE)  // 910,575

#define FLAG_INVALID 0u
#define FLAG_AGG     1u
#define FLAG_PREFIX  2u

__device__ uint32_t           g_hist16[NBKT / 2];   // two u16 counts per word
__device__ uint32_t           g_cursor[NBKT + 1];   // bucket starts + sentinel
__device__ uint32_t           g_kb[NCELL];
__device__ uint16_t           g_arr[NCELL];         // within-bucket arrival idx
__device__ unsigned long long g_sorted[SORTCAP];    // (kb<<21 | s) — validated
__device__ volatile uint32_t  g_status[NTILES];     // (sum << 2) | flag
__device__ uint32_t           g_ticket;

extern "C" __device__ float __nv_atan2f(float, float);

// JAX acos: acos(x) = 2*atan2(sqrt(1-x*x), 1+x); exact pi at x==-1.
__device__ __forceinline__ float acos_jax(float xq) {
    if (xq == -1.0f) return PI_F;
    float t  = __fsub_rn(1.0f, __fmul_rn(xq, xq));
    float sq = __fsqrt_rn(t);
    return __fmul_rn(2.0f, __nv_atan2f(sq, __fadd_rn(1.0f, xq)));
}

// Per-ring bucket mapping. Keys of ring k lie in [T-pi, T+pi], T = fl(2k*pi);
// bound +-3.2 guarantees containment. (kb - lo) >> sh < 2048, monotone.
// NOTE: sh can be LARGE for inner rings (small T -> tiny ulp -> huge bit
// span); only the full u64 (kb<<21 | s) comparator is order-exact.
__device__ __forceinline__ void ring_map(int k, uint32_t& lo, int& sh) {
    float T   = __fmul_rn((float)(2 * k), PI_F);
    float lof = fmaxf(__fsub_rn(T, 3.2f), 0.0f);
    float hif = __fadd_rn(T, 3.2f);
    lo = __float_as_uint(lof);
    uint32_t span = __float_as_uint(hif) - lo;
    int bn = 32 - __clz(span | 1);
    sh = (bn > 11) ? (bn - 11) : 0;
}

// ---------------------------------------------------------------------------
// K1: dense over x2>=0 half-plane; one thread -> key for its cell AND mirror
// (bit-exact: r, xq, A identical; phi*sign(x2) is an exact sign flip).
// The histogram atomicAdd's OLD value = within-bucket arrival index (g_arr).
// Also re-arms the scan bookkeeping (status/ticket) for this replay — status
// is only read by the scan kernel, which launches strictly after.
// ---------------------------------------------------------------------------
__global__ __launch_bounds__(256) void key_kernel() {
    int tid = blockIdx.x * blockDim.x + threadIdx.x;

    // Re-arm scan bookkeeping (hist is already zero: scan self-cleans it).
    if (tid < NTILES) g_status[tid] = FLAG_INVALID;
    if (tid == NTILES) g_ticket = 0;

    if (tid >= HALF_CELLS) return;
    int di = tid / SPIRAL_SIZE;
    int j  = tid - di * SPIRAL_SIZE;
    int i  = HALF + di;

    float x1 = (float)(j - HALF);
    float x2 = (float)di;
    float rr = __fadd_rn(__fmul_rn(x1, x1), __fmul_rn(x2, x2));
    float r  = __fsqrt_rn(rr);
    int   k  = (int)rintf(r);
    if (k > KMAX) return;

    float T = __fmul_rn(__fmul_rn(rintf(r), 2.0f), PI_F);
    uint32_t lo; int sh;
    ring_map(k, lo, sh);
    uint32_t bb = (uint32_t)k * BPR;

    int s = i * SPIRAL_SIZE + j;

    if (di == 0) {
        float phi = (x1 < 0.0f) ? PI_F : 0.0f;   // x2==0 row (NaN-fixed center)
        uint32_t kb = __float_as_uint(__fadd_rn(T, phi));
        g_kb[s] = kb;
        uint32_t b   = bb + ((kb - lo) >> sh);
        uint32_t old = atomicAdd(&g_hist16[b >> 1], 1u << ((b & 1u) * 16u));
        g_arr[s] = (uint16_t)((old >> ((b & 1u) * 16u)) & 0xFFFFu);
        return;
    }

    float A = acos_jax(__fdiv_rn(x1, r));

    uint32_t kb = __float_as_uint(__fadd_rn(T, A));      // phi = +A
    g_kb[s] = kb;
    uint32_t b   = bb + ((kb - lo) >> sh);
    uint32_t old = atomicAdd(&g_hist16[b >> 1], 1u << ((b & 1u) * 16u));
    g_arr[s] = (uint16_t)((old >> ((b & 1u) * 16u)) & 0xFFFFu);

    int sm = (2 * HALF - i) * SPIRAL_SIZE + j;
    uint32_t kbm = __float_as_uint(__fadd_rn(T, -A));    // mirror: phi = -A
    g_kb[sm] = kbm;
    uint32_t bm   = bb + ((kbm - lo) >> sh);
    uint32_t oldm = atomicAdd(&g_hist16[bm >> 1], 1u << ((bm & 1u) * 16u));
    g_arr[sm] = (uint16_t)((oldm >> ((bm & 1u) * 16u)) & 0xFFFFu);
}

// ---------------------------------------------------------------------------
// K2: single-pass exclusive scan hist16 -> g_cursor (decoupled lookback,
// ticket-ordered tiles). SELF-CLEANING: zeroes its hist words after reading,
// so the next replay's key_kernel starts from a clean histogram (hist is
// zero at every entry by induction; static zero-init covers the first call).
// Last tile writes sentinel g_cursor[NBKT].
// ---------------------------------------------------------------------------
__global__ __launch_bounds__(SCAN_BLK) void scan_kernel() {
    typedef cub::BlockScan<uint32_t, SCAN_BLK> BS;
    __shared__ typename BS::TempStorage tmp;
    __shared__ uint32_t s_tile;
    __shared__ uint32_t s_exclusive;

    if (threadIdx.x == 0) s_tile = atomicAdd(&g_ticket, 1u);
    __syncthreads();
    const uint32_t tile = s_tile;
    const int t = threadIdx.x;

    int widx = ((tile * SCAN_TILE + t * SCAN_ITEMS) >> 1) >> 1;  // uint2 index
    uint2 w = ((const uint2*)g_hist16)[widx];
    ((uint2*)g_hist16)[widx] = make_uint2(0u, 0u);   // self-clean for next replay
    uint32_t c0 = w.x & 0xFFFFu, c1 = w.x >> 16;
    uint32_t c2 = w.y & 0xFFFFu, c3 = w.y >> 16;
    uint32_t sum = c0 + c1 + c2 + c3;

    uint32_t tb, block_total;
    BS(tmp).ExclusiveSum(sum, tb, block_total);

    if (t == 0)
        g_status[tile] = (block_total << 2) |
                         (tile == 0 ? FLAG_PREFIX : FLAG_AGG);

    if (tile == 0) {
        if (t == 0) s_exclusive = 0;
    } else if (t < 32) {
        uint32_t excl = 0;
        int base = (int)tile;
        for (;;) {
            int idx = base - 32 + t;
            uint32_t st;
            if (idx >= 0) {
                do { st = g_status[idx]; } while ((st & 3u) == FLAG_INVALID);
            } else {
                st = FLAG_PREFIX;            // virtual zero-prefix before tile 0
            }
            uint32_t pmask = __ballot_sync(0xFFFFFFFFu, (st & 3u) == FLAG_PREFIX);
            int hp = 31 - __clz(pmask);
            uint32_t contrib = (t >= hp) ? (st >> 2) : 0u;
#pragma unroll
            for (int d = 16; d > 0; d >>= 1)
                contrib += __shfl_down_sync(0xFFFFFFFFu, contrib, d);
            contrib = __shfl_sync(0xFFFFFFFFu, contrib, 0);
            excl += contrib;
            if (pmask) break;
            base -= 32;
        }
        if (t == 0) {
            s_exclusive = excl;
            g_status[tile] = ((excl + block_total) << 2) | FLAG_PREFIX;
        }
    }
    __syncthreads();

    uint32_t run = s_exclusive + tb;
    uint4 o;
    o.x = run; run += c0;
    o.y = run; run += c1;
    o.z = run; run += c2;
    o.w = run;
    ((uint4*)g_cursor)[(tile * SCAN_TILE + t * SCAN_ITEMS) >> 2] = o;

    if (tile == NTILES - 1 && t == 0)
        g_cursor[NBKT] = s_exclusive + block_total;   // sentinel: total count
}

// K3: atomic-free scatter. pos = cursor[b] + arrival idx (unique); cursor
// stays pristine = exact bucket-start table for the gather. Staging only.
__global__ __launch_bounds__(256) void scatter_kernel() {
    int s = blockIdx.x * blockDim.x + threadIdx.x;
    if (s >= NCELL) return;
    int i = s / SPIRAL_SIZE, j = s - i * SPIRAL_SIZE;
    float x1 = (float)(j - HALF), x2 = (float)(i - HALF);
    float r = __fsqrt_rn(__fadd_rn(__fmul_rn(x1, x1), __fmul_rn(x2, x2)));
    int k = (int)rintf(r);
    if (k > KMAX) return;
    uint32_t lo; int sh;
    ring_map(k, lo, sh);
    uint32_t kb = g_kb[s];
    uint32_t b  = (uint32_t)k * BPR + ((kb - lo) >> sh);
    uint32_t pos = g_cursor[b] + (uint32_t)g_arr[s];
    g_sorted[pos] = ((unsigned long long)kb << 21) | (uint32_t)s;
}

// ---------------------------------------------------------------------------
// K4: fused rank + gather, LINEAR cell order (measured-fastest layout).
// rank = cursor[b] + #{bucket peers with smaller u64 packed value}
// (index-stable ties == jnp.argsort, validated rule); bucket bounds from
// adjacent cursor words. Invalid rings / rank tail write zeros.
// ---------------------------------------------------------------------------
__global__ __launch_bounds__(256) void gather_kernel(
        const float4* __restrict__ in, float4* __restrict__ out) {
    int s = blockIdx.x * blockDim.x + threadIdx.x;
    if (s >= NCELL) return;
    int i = s / SPIRAL_SIZE, j = s - i * SPIRAL_SIZE;
    float x1 = (float)(j - HALF), x2 = (float)(i - HALF);
    float r = __fsqrt_rn(__fadd_rn(__fmul_rn(x1, x1), __fmul_rn(x2, x2)));
    int k = (int)rintf(r);

    bool valid = (k <= KMAX);
    uint32_t rank = 0xFFFFFFFFu;
    if (valid) {
        uint32_t lo; int sh;
        ring_map(k, lo, sh);
        uint32_t kb  = g_kb[s];
        uint32_t b   = (uint32_t)k * BPR + ((kb - lo) >> sh);
        uint32_t st  = g_cursor[b];
        uint32_t end = g_cursor[b + 1];
        rank = st;
        if (end - st > 1) {
            unsigned long long my = ((unsigned long long)kb << 21) | (uint32_t)s;
            for (uint32_t q = st; q < end; q++)
                rank += (g_sorted[q] < my) ? 1u : 0u;
        }
        valid = (rank < (uint32_t)SIGLEN);
    }

    float4 z = make_float4(0.0f, 0.0f, 0.0f, 0.0f);
#pragma unroll
    for (int b = 0; b < NBATCH; b++) {
        float4 w = z;
        if (valid) w = __ldg(&in[(size_t)b * SIGLEN + rank]);
        __stcs(&out[(size_t)b * NCELL + s], w);
    }
}

extern "C" void kernel_launch(void* const* d_in, const int* in_sizes, int n_in,
                              void* d_out, int out_size) {
    (void)in_sizes; (void)n_in; (void)out_size;

    key_kernel<<<(HALF_CELLS + 255) / 256, 256>>>();
    scan_kernel<<<NTILES, SCAN_BLK>>>();
    scatter_kernel<<<(NCELL + 255) / 256, 256>>>();
    gather_kernel<<<(NCELL + 255) / 256, 256>>>(
        (const float4*)d_in[0], (float4*)d_out);
}

// round 16
// speedup vs baseline: 1.1958x; 1.0009x over previous
#include <cuda_runtime.h>
#include <cub/cub.cuh>
#include <cstdint>

// Problem constants (B=8, L=1e6, C=4 -> size=1349)
#define SPIRAL_SIZE 1349
#define HALF        674
#define NCELL       (SPIRAL_SIZE * SPIRAL_SIZE)   // 1,819,801 < 2^21
#define SIGLEN      1000000
#define NBATCH      8

#define PI_F 3.14159274101257324f   // fl(pi)

// Validity cutoff (validated rel_err==0.0): rings 0..564 cover all ranks < 1e6.
#define KMAX   564
#define NRV    (KMAX + 1)
#define BPR    2048                 // buckets per ring
#define NBKT   (NRV * BPR)          // 1,157,120

#define SCAN_BLK   512
#define SCAN_ITEMS 4
#define SCAN_TILE  (SCAN_BLK * SCAN_ITEMS)  // 2048 == BPR
#define NTILES     (NBKT / SCAN_TILE)       // 565 exact

#define SORTCAP     1100000                 // > total valid cells (~1.0012M)
#define HALF_ROWS   (HALF + 1)
#define HALF_CELLS  (HALF_ROWS * SPIRAL_SIZE)  // 910,575

#define FLAG_INVALID 0u
#define FLAG_AGG     1u
#define FLAG_PREFIX  2u

__device__ uint32_t           g_hist16[NBKT / 2];   // two u16 counts per word
__device__ uint32_t           g_cursor[NBKT + 1];   // bucket starts + sentinel
__device__ uint32_t           g_kb[NCELL];
__device__ uint16_t           g_arr[NCELL];         // within-bucket arrival idx
__device__ unsigned long long g_sorted[SORTCAP];    // (kb<<21 | s) — validated
__device__ volatile uint32_t  g_status[NTILES];     // (sum << 2) | flag
__device__ uint32_t           g_ticket;

extern "C" __device__ float __nv_atan2f(float, float);

// JAX acos: acos(x) = 2*atan2(sqrt(1-x*x), 1+x); exact pi at x==-1.
__device__ __forceinline__ float acos_jax(float xq) {
    if (xq == -1.0f) return PI_F;
    float t  = __fsub_rn(1.0f, __fmul_rn(xq, xq));
    float sq = __fsqrt_rn(t);
    return __fmul_rn(2.0f, __nv_atan2f(sq, __fadd_rn(1.0f, xq)));
}

// Per-ring bucket mapping. Keys of ring k lie in [T-pi, T+pi], T = fl(2k*pi);
// bound +-3.2 guarantees containment. (kb - lo) >> sh < 2048, monotone.
// sh can be LARGE for inner rings; only the u64 comparator is order-exact.
__device__ __forceinline__ void ring_map(int k, uint32_t& lo, int& sh) {
    float T   = __fmul_rn((float)(2 * k), PI_F);
    float lof = fmaxf(__fsub_rn(T, 3.2f), 0.0f);
    float hif = __fadd_rn(T, 3.2f);
    lo = __float_as_uint(lof);
    uint32_t span = __float_as_uint(hif) - lo;
    int bn = 32 - __clz(span | 1);
    sh = (bn > 11) ? (bn - 11) : 0;
}

// ---------------------------------------------------------------------------
// K1: dense over x2>=0 half-plane; one thread -> key for its cell AND mirror
// (bit-exact: r, xq, A identical; phi*sign(x2) is an exact sign flip).
// The histogram atomicAdd's OLD value = within-bucket arrival index (g_arr).
// Also re-arms the scan bookkeeping (status/ticket) for this replay.
// ---------------------------------------------------------------------------
__global__ __launch_bounds__(256) void key_kernel() {
    int tid = blockIdx.x * blockDim.x + threadIdx.x;

    // Re-arm scan bookkeeping (hist is already zero: scan self-cleans it).
    if (tid < NTILES) g_status[tid] = FLAG_INVALID;
    if (tid == NTILES) g_ticket = 0;

    if (tid >= HALF_CELLS) return;
    int di = tid / SPIRAL_SIZE;
    int j  = tid - di * SPIRAL_SIZE;
    int i  = HALF + di;

    float x1 = (float)(j - HALF);
    float x2 = (float)di;
    float rr = __fadd_rn(__fmul_rn(x1, x1), __fmul_rn(x2, x2));
    float r  = __fsqrt_rn(rr);
    int   k  = (int)rintf(r);
    if (k > KMAX) return;

    float T = __fmul_rn(__fmul_rn(rintf(r), 2.0f), PI_F);
    uint32_t lo; int sh;
    ring_map(k, lo, sh);
    uint32_t bb = (uint32_t)k * BPR;

    int s = i * SPIRAL_SIZE + j;

    if (di == 0) {
        float phi = (x1 < 0.0f) ? PI_F : 0.0f;   // x2==0 row (NaN-fixed center)
        uint32_t kb = __float_as_uint(__fadd_rn(T, phi));
        g_kb[s] = kb;
        uint32_t b   = bb + ((kb - lo) >> sh);
        uint32_t old = atomicAdd(&g_hist16[b >> 1], 1u << ((b & 1u) * 16u));
        g_arr[s] = (uint16_t)((old >> ((b & 1u) * 16u)) & 0xFFFFu);
        return;
    }

    float A = acos_jax(__fdiv_rn(x1, r));

    uint32_t kb = __float_as_uint(__fadd_rn(T, A));      // phi = +A
    g_kb[s] = kb;
    uint32_t b   = bb + ((kb - lo) >> sh);
    uint32_t old = atomicAdd(&g_hist16[b >> 1], 1u << ((b & 1u) * 16u));
    g_arr[s] = (uint16_t)((old >> ((b & 1u) * 16u)) & 0xFFFFu);

    int sm = (2 * HALF - i) * SPIRAL_SIZE + j;
    uint32_t kbm = __float_as_uint(__fadd_rn(T, -A));    // mirror: phi = -A
    g_kb[sm] = kbm;
    uint32_t bm   = bb + ((kbm - lo) >> sh);
    uint32_t oldm = atomicAdd(&g_hist16[bm >> 1], 1u << ((bm & 1u) * 16u));
    g_arr[sm] = (uint16_t)((oldm >> ((bm & 1u) * 16u)) & 0xFFFFu);
}

// ---------------------------------------------------------------------------
// K2: single-pass exclusive scan hist16 -> g_cursor (decoupled lookback,
// ticket-ordered tiles). SELF-CLEANING: zeroes its hist words after reading
// (hist is zero at every entry by induction; static zero-init covers the
// first call). Last tile writes sentinel g_cursor[NBKT].
// ---------------------------------------------------------------------------
__global__ __launch_bounds__(SCAN_BLK) void scan_kernel() {
    typedef cub::BlockScan<uint32_t, SCAN_BLK> BS;
    __shared__ typename BS::TempStorage tmp;
    __shared__ uint32_t s_tile;
    __shared__ uint32_t s_exclusive;

    if (threadIdx.x == 0) s_tile = atomicAdd(&g_ticket, 1u);
    __syncthreads();
    const uint32_t tile = s_tile;
    const int t = threadIdx.x;

    int widx = ((tile * SCAN_TILE + t * SCAN_ITEMS) >> 1) >> 1;  // uint2 index
    uint2 w = ((const uint2*)g_hist16)[widx];
    ((uint2*)g_hist16)[widx] = make_uint2(0u, 0u);   // self-clean for next replay
    uint32_t c0 = w.x & 0xFFFFu, c1 = w.x >> 16;
    uint32_t c2 = w.y & 0xFFFFu, c3 = w.y >> 16;
    uint32_t sum = c0 + c1 + c2 + c3;

    uint32_t tb, block_total;
    BS(tmp).ExclusiveSum(sum, tb, block_total);

    if (t == 0)
        g_status[tile] = (block_total << 2) |
                         (tile == 0 ? FLAG_PREFIX : FLAG_AGG);

    if (tile == 0) {
        if (t == 0) s_exclusive = 0;
    } else if (t < 32) {
        uint32_t excl = 0;
        int base = (int)tile;
        for (;;) {
            int idx = base - 32 + t;
            uint32_t st;
            if (idx >= 0) {
                do { st = g_status[idx]; } while ((st & 3u) == FLAG_INVALID);
            } else {
                st = FLAG_PREFIX;            // virtual zero-prefix before tile 0
            }
            uint32_t pmask = __ballot_sync(0xFFFFFFFFu, (st & 3u) == FLAG_PREFIX);
            int hp = 31 - __clz(pmask);
            uint32_t contrib = (t >= hp) ? (st >> 2) : 0u;
#pragma unroll
            for (int d = 16; d > 0; d >>= 1)
                contrib += __shfl_down_sync(0xFFFFFFFFu, contrib, d);
            contrib = __shfl_sync(0xFFFFFFFFu, contrib, 0);
            excl += contrib;
            if (pmask) break;
            base -= 32;
        }
        if (t == 0) {
            s_exclusive = excl;
            g_status[tile] = ((excl + block_total) << 2) | FLAG_PREFIX;
        }
    }
    __syncthreads();

    uint32_t run = s_exclusive + tb;
    uint4 o;
    o.x = run; run += c0;
    o.y = run; run += c1;
    o.z = run; run += c2;
    o.w = run;
    ((uint4*)g_cursor)[(tile * SCAN_TILE + t * SCAN_ITEMS) >> 2] = o;

    if (tile == NTILES - 1 && t == 0)
        g_cursor[NBKT] = s_exclusive + block_total;   // sentinel: total count
}

// ---------------------------------------------------------------------------
// K3: atomic-free scatter + invalid-cell zero-fill (R9-measured: ~23.5us).
// Valid cells stage packed (kb<<21 | s) at cursor[b] + arrival idx (unique;
// cursor stays pristine). Invalid cells (k > KMAX) write their 8 zero output
// rows HERE — coalesced row-runs — so the gather never touches them.
// ---------------------------------------------------------------------------
__global__ __launch_bounds__(256) void scatter_kernel(float4* __restrict__ out) {
    int s = blockIdx.x * blockDim.x + threadIdx.x;
    if (s >= NCELL) return;
    int i = s / SPIRAL_SIZE, j = s - i * SPIRAL_SIZE;
    float x1 = (float)(j - HALF), x2 = (float)(i - HALF);
    float r = __fsqrt_rn(__fadd_rn(__fmul_rn(x1, x1), __fmul_rn(x2, x2)));
    int k = (int)rintf(r);
    if (k > KMAX) {
        float4 z = make_float4(0.0f, 0.0f, 0.0f, 0.0f);
#pragma unroll
        for (int b = 0; b < NBATCH; b++)
            __stcs(&out[(size_t)b * NCELL + s], z);
        return;
    }
    uint32_t lo; int sh;
    ring_map(k, lo, sh);
    uint32_t kb = g_kb[s];
    uint32_t b  = (uint32_t)k * BPR + ((kb - lo) >> sh);
    uint32_t pos = g_cursor[b] + (uint32_t)g_arr[s];
    g_sorted[pos] = ((unsigned long long)kb << 21) | (uint32_t)s;
}

// ---------------------------------------------------------------------------
// K4: fused rank + gather, LINEAR cell order, VALID CELLS ONLY writes.
// Invalid cells were zero-filled by the scatter, so this kernel's write
// stream shrinks 233 -> 128 MB (valid cells form one contiguous span per
// row -> sector-dense). rank = cursor[b] + #{bucket peers with smaller u64
// packed value} (index-stable ties == jnp.argsort, validated rule).
// Valid-ring rank-tail cells (rank >= L) still write zeros (tiny count).
// ---------------------------------------------------------------------------
__global__ __launch_bounds__(256) void gather_kernel(
        const float4* __restrict__ in, float4* __restrict__ out) {
    int s = blockIdx.x * blockDim.x + threadIdx.x;
    if (s >= NCELL) return;
    int i = s / SPIRAL_SIZE, j = s - i * SPIRAL_SIZE;
    float x1 = (float)(j - HALF), x2 = (float)(i - HALF);
    float r = __fsqrt_rn(__fadd_rn(__fmul_rn(x1, x1), __fmul_rn(x2, x2)));
    int k = (int)rintf(r);
    if (k > KMAX) return;            // zero-filled by scatter

    uint32_t lo; int sh;
    ring_map(k, lo, sh);
    uint32_t kb  = g_kb[s];
    uint32_t b   = (uint32_t)k * BPR + ((kb - lo) >> sh);
    uint32_t st  = g_cursor[b];
    uint32_t end = g_cursor[b + 1];
    uint32_t rank = st;
    if (end - st > 1) {
        unsigned long long my = ((unsigned long long)kb << 21) | (uint32_t)s;
        for (uint32_t q = st; q < end; q++)
            rank += (g_sorted[q] < my) ? 1u : 0u;
    }
    bool valid = (rank < (uint32_t)SIGLEN);

    float4 z = make_float4(0.0f, 0.0f, 0.0f, 0.0f);
#pragma unroll
    for (int b2 = 0; b2 < NBATCH; b2++) {
        float4 w = z;
        if (valid) w = __ldg(&in[(size_t)b2 * SIGLEN + rank]);
        __stcs(&out[(size_t)b2 * NCELL + s], w);
    }
}

extern "C" void kernel_launch(void* const* d_in, const int* in_sizes, int n_in,
                              void* d_out, int out_size) {
    (void)in_sizes; (void)n_in; (void)out_size;

    key_kernel<<<(HALF_CELLS + 255) / 256, 256>>>();
    scan_kernel<<<NTILES, SCAN_BLK>>>();
    scatter_kernel<<<(NCELL + 255) / 256, 256>>>((float4*)d_out);
    gather_kernel<<<(NCELL + 255) / 256, 256>>>(
        (const float4*)d_in[0], (float4*)d_out);
}